// round 6
// baseline (speedup 1.0000x reference)
#include <cuda_runtime.h>
#include <cuda_bf16.h>

#define BQ 8
#define NQ 8192
#define MK 2048
#define CC 256
#define EPSW 1e-8f
#define GSZ 16
#define NGROUP (MK / GSZ)   // 128 groups of 16 points

// Compact per-query result: (w0, w1, bitcast(i0 | i1<<16), bitcast(i2))
__device__ float4 g_wp[BQ * NQ];

// ---------------------------------------------------------------------------
// f32x2 packed helpers
// ---------------------------------------------------------------------------
typedef unsigned long long u64t;
__device__ __forceinline__ u64t fma2(u64t a, u64t b, u64t c) {
    u64t d; asm("fma.rn.f32x2 %0, %1, %2, %3;" : "=l"(d) : "l"(a), "l"(b), "l"(c));
    return d;
}
__device__ __forceinline__ u64t add2(u64t a, u64t b) {
    u64t d; asm("add.rn.f32x2 %0, %1, %2;" : "=l"(d) : "l"(a), "l"(b));
    return d;
}
__device__ __forceinline__ u64t mul2(u64t a, u64t b) {
    u64t d; asm("mul.rn.f32x2 %0, %1, %2;" : "=l"(d) : "l"(a), "l"(b));
    return d;
}
__device__ __forceinline__ u64t pack2(float lo, float hi) {
    u64t d; asm("mov.b64 %0, {%1, %2};" : "=l"(d) : "f"(lo), "f"(hi));
    return d;
}
__device__ __forceinline__ void unpack2(u64t v, float& lo, float& hi) {
    asm("mov.b64 {%0, %1}, %2;" : "=f"(lo), "=f"(hi) : "l"(v));
}

// ---------------------------------------------------------------------------
// Kernel 1: three_nn + weights. EXACT d^2 everywhere (selection must match
// the reference ordering bit-for-bit in practice — one wrong neighbor across
// 65536 queries is enough to fail the 1e-3 gate).
// Groups of 16 ranked by exact group-min; top-3 groups provably contain the
// exact top-3 points. Finale: exact top-3 over 48 candidates, ascending
// index order preserves jax's lower-index tie-break.
// Block 128, 1 query/thread, grid (NQ/128, BQ) = 512 blocks.
// ---------------------------------------------------------------------------
__global__ void __launch_bounds__(128) nn_kernel(
    const float* __restrict__ unknown,   // (B, N, 3)
    const float* __restrict__ known)     // (B, M, 3)
{
    __shared__ float4 sXY[MK / 2];   // (x0,x1,y0,y1) per point-pair, 16 KB
    __shared__ float  sZ[MK];        // 8 KB

    const int b = blockIdx.y;
    {
        const float2* kb2 = (const float2*)(known + (size_t)b * MK * 3);
        for (int i = threadIdx.x; i < MK / 2; i += 128) {
            float2 p0 = kb2[i * 3 + 0];   // x0 y0
            float2 p1 = kb2[i * 3 + 1];   // z0 x1
            float2 p2 = kb2[i * 3 + 2];   // y1 z1
            sXY[i] = make_float4(p0.x, p1.y, p0.y, p2.x);
            sZ[2 * i]     = p1.x;
            sZ[2 * i + 1] = p2.y;
        }
    }
    __syncthreads();

    const int n = blockIdx.x * 128 + threadIdx.x;
    const float* u = unknown + ((size_t)b * NQ + n) * 3;
    const float ux = u[0], uy = u[1], uz = u[2];
    const u64t nux = pack2(-ux, -ux);
    const u64t nuy = pack2(-uy, -uy);
    const u64t nuz = pack2(-uz, -uz);

    // top-3 group mins (sorted ascending) + group ids
    float v0 = 1e30f, v1 = 1e30f, v2 = 1e30f;
    int   q0 = 0, q1 = 0, q2 = 0;

    const ulonglong2* pXY = (const ulonglong2*)sXY;
    const ulonglong2* pZ  = (const ulonglong2*)sZ;

#pragma unroll 2
    for (int g = 0; g < NGROUP; g++) {
        float s[16];
#pragma unroll
        for (int pp = 0; pp < 8; pp++) {
            ulonglong2 A = pXY[8 * g + pp];          // x-pair, y-pair
            u64t zpair = (pp & 1) ? pZ[4 * g + (pp >> 1)].y
                                  : pZ[4 * g + (pp >> 1)].x;
            u64t dx = add2(A.x, nux);
            u64t dy = add2(A.y, nuy);
            u64t dz = add2(zpair, nuz);
            u64t acc = fma2(dx, dx, fma2(dy, dy, mul2(dz, dz)));
            unpack2(acc, s[2 * pp], s[2 * pp + 1]);
        }
        // 15-FMNMX min tree over 16 exact d^2
        float m01 = fminf(s[0], s[1]),   m23 = fminf(s[2], s[3]);
        float m45 = fminf(s[4], s[5]),   m67 = fminf(s[6], s[7]);
        float m89 = fminf(s[8], s[9]),   mab = fminf(s[10], s[11]);
        float mcd = fminf(s[12], s[13]), mef = fminf(s[14], s[15]);
        float t0 = fminf(m01, m23), t1 = fminf(m45, m67);
        float t2 = fminf(m89, mab), t3 = fminf(mcd, mef);
        float m = fminf(fminf(t0, t1), fminf(t2, t3));

        // branchless sorted insert of (m, g); strict < keeps earlier (lower g)
        bool c0 = m < v0, c1 = m < v1, c2 = m < v2;
        float nv0 = c0 ? m  : v0;
        float nv1 = c0 ? v0 : (c1 ? m  : v1);
        float nv2 = c1 ? v1 : (c2 ? m  : v2);
        int   ng0 = c0 ? g  : q0;
        int   ng1 = c0 ? q0 : (c1 ? g  : q1);
        int   ng2 = c1 ? q1 : (c2 ? g  : q2);
        v0 = nv0; v1 = nv1; v2 = nv2;
        q0 = ng0; q1 = ng1; q2 = ng2;
    }

    // Iterate winning groups in ascending id (jax lower-index tie-break).
    int ha = min(q0, min(q1, q2));
    int hc = max(q0, max(q1, q2));
    int hb = q0 + q1 + q2 - ha - hc;
    int grp[3] = { ha, hb, hc };

    // Finale: exact top-3 over the 48 candidate points.
    float d0 = 1e30f, d1 = 1e30f, d2v = 1e30f;
    int   i0 = 0, i1 = 0, i2 = 0;
#pragma unroll
    for (int t = 0; t < 3; t++) {
        const int mb = grp[t] * GSZ;
#pragma unroll
        for (int k = 0; k < GSZ; k++) {
            const int m = mb + k;
            const int p = m >> 1, h = m & 1;
            float4 XY = sXY[p];
            float kx = h ? XY.y : XY.x;
            float ky = h ? XY.w : XY.z;
            float kz = sZ[m];
            float dx = kx - ux, dy = ky - uy, dz = kz - uz;
            float d2 = fmaf(dx, dx, fmaf(dy, dy, dz * dz));
            bool c0b = d2 < d0, c1b = d2 < d1, c2b = d2 < d2v;
            float t0 = c0b ? d2 : d0;
            float t1 = c0b ? d0 : (c1b ? d2 : d1);
            float t2 = c1b ? d1 : (c2b ? d2 : d2v);
            int   j0 = c0b ? m  : i0;
            int   j1 = c0b ? i0 : (c1b ? m  : i1);
            int   j2 = c1b ? i1 : (c2b ? m  : i2);
            d0 = t0; d1 = t1; d2v = t2;
            i0 = j0; i1 = j1; i2 = j2;
        }
    }

    const float r0 = 1.0f / (d0 + EPSW);
    const float r1 = 1.0f / (d1 + EPSW);
    const float r2 = 1.0f / (d2v + EPSW);
    const float s  = 1.0f / (r0 + r1 + r2);
    g_wp[(size_t)b * NQ + n] =
        make_float4(r0 * s, r1 * s,
                    __int_as_float(i0 | (i1 << 16)),
                    __int_as_float(i2));
}

// ---------------------------------------------------------------------------
// Kernel 2: three_interpolate, m-major transposed smem + packed f32x2 FMAs.
// Grid (CC/4, BQ) = 512 blocks, block 256. smem rowsT[m][c0..c0+3] (32 KB).
// Each thread: 4 queries/iter; per query 3 LDS.128 gathers, 6 FFMA2.
// ---------------------------------------------------------------------------
#define CG 4

__global__ void __launch_bounds__(256) interp_kernel(
    const float* __restrict__ feats,     // (B, C, M)
    float* __restrict__ out)             // (B, C, N)
{
    __shared__ float rowsT[MK * CG];     // 32 KB

    const int b  = blockIdx.y;
    const int c0 = blockIdx.x * CG;

    {
        const float* fp = feats + ((size_t)b * CC + c0) * MK;
#pragma unroll
        for (int it = 0; it < MK / 256; it++) {
            const int m = it * 256 + threadIdx.x;
            float a  = fp[m];
            float bb = fp[MK + m];
            float c  = fp[2 * MK + m];
            float d  = fp[3 * MK + m];
            *(float4*)&rowsT[m * 4] = make_float4(a, bb, c, d);
        }
    }
    __syncthreads();

    const float4* wp = (const float4*)&g_wp[(size_t)b * NQ];
    float* outp = out + ((size_t)b * CC + c0) * NQ;

    for (int it = 0; it < NQ / 1024; it++) {   // 8 iters
        const int n0 = it * 1024 + threadIdx.x * 4;

        float vq[4][4];   // [query][channel]
#pragma unroll
        for (int q = 0; q < 4; q++) {
            float4 W = wp[n0 + q];
            float w0 = W.x, w1 = W.y;
            float w2 = 1.0f - w0 - w1;
            unsigned pk = __float_as_uint(W.z);
            int j0 = pk & 0xFFFF;
            int j1 = pk >> 16;
            int j2 = __float_as_uint(W.w);

            const ulonglong2* r0p = (const ulonglong2*)&rowsT[j0 * 4];
            const ulonglong2* r1p = (const ulonglong2*)&rowsT[j1 * 4];
            const ulonglong2* r2p = (const ulonglong2*)&rowsT[j2 * 4];
            ulonglong2 f0 = *r0p;
            ulonglong2 f1 = *r1p;
            ulonglong2 f2 = *r2p;

            u64t w0p = pack2(w0, w0);
            u64t w1p = pack2(w1, w1);
            u64t w2p = pack2(w2, w2);

            u64t lo = fma2(w0p, f0.x, fma2(w1p, f1.x, mul2(w2p, f2.x)));
            u64t hi = fma2(w0p, f0.y, fma2(w1p, f1.y, mul2(w2p, f2.y)));
            unpack2(lo, vq[q][0], vq[q][1]);
            unpack2(hi, vq[q][2], vq[q][3]);
        }

#pragma unroll
        for (int c = 0; c < CG; c++) {
            float4 v = make_float4(vq[0][c], vq[1][c], vq[2][c], vq[3][c]);
            *(float4*)(outp + (size_t)c * NQ + n0) = v;
        }
    }
}

// ---------------------------------------------------------------------------
// Launch
// ---------------------------------------------------------------------------
extern "C" void kernel_launch(void* const* d_in, const int* in_sizes, int n_in,
                              void* d_out, int out_size)
{
    const float* unknown = (const float*)d_in[0];   // (8, 8192, 3)
    const float* known   = (const float*)d_in[1];   // (8, 2048, 3)
    const float* feats   = (const float*)d_in[2];   // (8, 256, 2048)
    float* out = (float*)d_out;                     // (8, 256, 8192)

    dim3 g1(NQ / 128, BQ);
    nn_kernel<<<g1, 128>>>(unknown, known);

    dim3 g2(CC / CG, BQ);
    interp_kernel<<<g2, 256>>>(feats, out);
}